// round 13
// baseline (speedup 1.0000x reference)
#include <cuda_runtime.h>

// Problem constants (fixed by the dataset)
#define NN    50000
#define EE    800000
#define FND   8
#define TIN   8
#define HIDN  16
#define TOUTN 4
#define SLOTS 11   // 8 initial time slices + 3 propagated h's
#define ROWF  (SLOTS * FND)   // 88 floats per node row in g_Px

// Scratch (device globals: no allocation allowed)
__device__ int   g_cnt[NN];
__device__ int   g_pos[NN];
__device__ int   g_off[NN];
__device__ int   g_total;
__device__ int   g_csr[EE];              // src list grouped by dst
__device__ float g_dinv[NN];
__device__ float g_nself[NN];
__device__ float g_Px[(size_t)NN * ROWF];   // [n][slot][f], 17.6 MB
__device__ float g_hbuf[2][(size_t)NN * FND];  // double-buffered h (race-free)
__device__ float g_M[3 * 128];           // folded W@L_top per gate (8x16)
__device__ float g_fb[3 * 16];           // folded bias b@L_top + Lb per gate

// ---------------------------------------------------------------------------
__global__ void k_zero_int(int N) {
    int i = blockIdx.x * blockDim.x + threadIdx.x;
    if (i < N) { g_cnt[i] = 0; g_pos[i] = 0; }
    if (i == 0) g_total = 0;
}

__global__ void k_cnt(const int* __restrict__ ei, int E) {
    int i = blockIdx.x * blockDim.x + threadIdx.x;
    if (i < E) atomicAdd(&g_cnt[ei[E + i]], 1);   // dst = ei[E + e]
}

__global__ void k_norm(int N) {
    int i = blockIdx.x * blockDim.x + threadIdx.x;
    if (i < N) {
        float d = (float)g_cnt[i] + 1.0f;
        g_dinv[i]  = rsqrtf(d);
        g_nself[i] = __fdividef(1.0f, d);   // dinv*dinv
    }
}

// Fold the two-layer gate algebra:
//   concat(P@W + b, H) @ L + Lb  ==  P@(W@L_top) + (b@L_top + Lb) + H@L_bot
__global__ void k_fold(const float* __restrict__ Wz, const float* __restrict__ bz,
                       const float* __restrict__ Lzw, const float* __restrict__ Lzb,
                       const float* __restrict__ Wr, const float* __restrict__ br,
                       const float* __restrict__ Lrw, const float* __restrict__ Lrb,
                       const float* __restrict__ Wh, const float* __restrict__ bh,
                       const float* __restrict__ Lhw, const float* __restrict__ Lhb) {
    int t = threadIdx.x;
    if (t >= 48) return;
    int gate = t >> 4;
    int j = t & 15;
    const float *W, *b, *L, *Lb;
    if      (gate == 0) { W = Wz; b = bz; L = Lzw; Lb = Lzb; }
    else if (gate == 1) { W = Wr; b = br; L = Lrw; Lb = Lrb; }
    else                { W = Wh; b = bh; L = Lhw; Lb = Lhb; }
#pragma unroll
    for (int k = 0; k < 8; k++) {
        float m = 0.0f;
#pragma unroll
        for (int i = 0; i < 16; i++) m = fmaf(W[k * 16 + i], L[i * 16 + j], m);
        g_M[gate * 128 + k * 16 + j] = m;
    }
    float fb = Lb[j];
#pragma unroll
    for (int i = 0; i < 16; i++) fb = fmaf(b[i], L[i * 16 + j], fb);
    g_fb[gate * 16 + j] = fb;
}

// Unordered CSR slot allocation: per-block scan + one global atomicAdd.
__global__ void k_alloc(int N) {
    __shared__ int wsum[8];
    __shared__ int sbase;
    int i = blockIdx.x * 256 + threadIdx.x;
    int lane = threadIdx.x & 31;
    int wid  = threadIdx.x >> 5;
    int c = (i < N) ? g_cnt[i] : 0;
    int v = c;
#pragma unroll
    for (int d = 1; d < 32; d <<= 1) {
        int u = __shfl_up_sync(0xffffffffu, v, d);
        if (lane >= d) v += u;
    }
    if (lane == 31) wsum[wid] = v;
    __syncthreads();
    if (threadIdx.x < 8) {
        int w = wsum[threadIdx.x];
#pragma unroll
        for (int d = 1; d < 8; d <<= 1) {
            int u = __shfl_up_sync(0xffu, w, d, 8);
            if (threadIdx.x >= (unsigned)d) w += u;
        }
        wsum[threadIdx.x] = w;
        if (threadIdx.x == 7) sbase = atomicAdd(&g_total, w);
    }
    __syncthreads();
    int excl = v - c + (wid > 0 ? wsum[wid - 1] : 0) + sbase;
    if (i < N) g_off[i] = excl;
}

__global__ void k_scatter(const int* __restrict__ ei, int E) {
    int e = blockIdx.x * blockDim.x + threadIdx.x;
    if (e >= E) return;
    int d = ei[E + e];
    int p = atomicAdd(&g_pos[d], 1);
    g_csr[g_off[d] + p] = ei[e];
}

__device__ __forceinline__ float sigmoid_f(float x) {
    return __fdividef(1.0f, 1.0f + __expf(-x));
}
__device__ __forceinline__ float tanh_f(float x) {
    float e = __expf(-2.0f * x);
    return __fdividef(1.0f - e, 1.0f + e);
}

// One 16B weight load feeds BOTH nodes (8 FMAs per LDS.128).
#define ROWFMA2(BASE, ROW, VA, VB) do {                                   \
    float4 w_ = *(const float4*)((BASE) + (ROW) * 16 + q4);               \
    cA0 = fmaf((VA), w_.x, cA0); cA1 = fmaf((VA), w_.y, cA1);             \
    cA2 = fmaf((VA), w_.z, cA2); cA3 = fmaf((VA), w_.w, cA3);             \
    cB0 = fmaf((VB), w_.x, cB0); cB1 = fmaf((VB), w_.y, cB1);             \
    cB2 = fmaf((VB), w_.z, cB2); cB3 = fmaf((VB), w_.w, cB3); } while (0)

// Layer-1 folded: 8 input features through the 8x16 M matrix, two nodes at once
#define DOT8P2(BASE) do {                                                 \
    ROWFMA2(BASE, 0, qaA.x, qaB.x);                                       \
    ROWFMA2(BASE, 1, qaA.y, qaB.y);                                       \
    ROWFMA2(BASE, 2, qaA.z, qaB.z);                                       \
    ROWFMA2(BASE, 3, qaA.w, qaB.w);                                       \
    ROWFMA2(BASE, 4, qbA.x, qbB.x);                                       \
    ROWFMA2(BASE, 5, qbA.y, qbB.y);                                       \
    ROWFMA2(BASE, 6, qbA.z, qbB.z);                                       \
    ROWFMA2(BASE, 7, qbA.w, qbB.w); } while (0)

// Gather 16 per-unit values spread 4-per-lane across the 4-lane node group
#define BCAST16(P, S0, S1, S2, S3) do {                                   \
    P##0  = __shfl_sync(0xffffffffu, S0, 0, 4);                           \
    P##1  = __shfl_sync(0xffffffffu, S1, 0, 4);                           \
    P##2  = __shfl_sync(0xffffffffu, S2, 0, 4);                           \
    P##3  = __shfl_sync(0xffffffffu, S3, 0, 4);                           \
    P##4  = __shfl_sync(0xffffffffu, S0, 1, 4);                           \
    P##5  = __shfl_sync(0xffffffffu, S1, 1, 4);                           \
    P##6  = __shfl_sync(0xffffffffu, S2, 1, 4);                           \
    P##7  = __shfl_sync(0xffffffffu, S3, 1, 4);                           \
    P##8  = __shfl_sync(0xffffffffu, S0, 2, 4);                           \
    P##9  = __shfl_sync(0xffffffffu, S1, 2, 4);                           \
    P##10 = __shfl_sync(0xffffffffu, S2, 2, 4);                           \
    P##11 = __shfl_sync(0xffffffffu, S3, 2, 4);                           \
    P##12 = __shfl_sync(0xffffffffu, S0, 3, 4);                           \
    P##13 = __shfl_sync(0xffffffffu, S1, 3, 4);                           \
    P##14 = __shfl_sync(0xffffffffu, S2, 3, 4);                           \
    P##15 = __shfl_sync(0xffffffffu, S3, 3, 4); } while (0)

// 16 broadcast values (per node) times 16 rows of the H-portion matrix
#define DOT16H(BASE, PA, PB) do {                                         \
    ROWFMA2(BASE, 0,  PA##0,  PB##0);                                     \
    ROWFMA2(BASE, 1,  PA##1,  PB##1);                                     \
    ROWFMA2(BASE, 2,  PA##2,  PB##2);                                     \
    ROWFMA2(BASE, 3,  PA##3,  PB##3);                                     \
    ROWFMA2(BASE, 4,  PA##4,  PB##4);                                     \
    ROWFMA2(BASE, 5,  PA##5,  PB##5);                                     \
    ROWFMA2(BASE, 6,  PA##6,  PB##6);                                     \
    ROWFMA2(BASE, 7,  PA##7,  PB##7);                                     \
    ROWFMA2(BASE, 8,  PA##8,  PB##8);                                     \
    ROWFMA2(BASE, 9,  PA##9,  PB##9);                                     \
    ROWFMA2(BASE, 10, PA##10, PB##10);                                    \
    ROWFMA2(BASE, 11, PA##11, PB##11);                                    \
    ROWFMA2(BASE, 12, PA##12, PB##12);                                    \
    ROWFMA2(BASE, 13, PA##13, PB##13);                                    \
    ROWFMA2(BASE, 14, PA##14, PB##14);                                    \
    ROWFMA2(BASE, 15, PA##15, PB##15); } while (0)

// Per-node output projection + stores. g_hbuf[o&1] is this scan's write buffer.
#define EPILOGUE(AX0, AX1, AX2, AX3, NODE, VALID) do {                    \
    float r0 = fmaxf(AX0, 0.f), r1 = fmaxf(AX1, 0.f);                     \
    float r2 = fmaxf(AX2, 0.f), r3 = fmaxf(AX3, 0.f);                     \
    float o0 = OUTF(0), o1 = OUTF(1), o2 = OUTF(2), o3 = OUTF(3);         \
    float o4 = OUTF(4), o5 = OUTF(5), o6 = OUTF(6), o7 = OUTF(7);         \
    o0 += __shfl_xor_sync(0xffffffffu, o0, 1, 4);                         \
    o1 += __shfl_xor_sync(0xffffffffu, o1, 1, 4);                         \
    o2 += __shfl_xor_sync(0xffffffffu, o2, 1, 4);                         \
    o3 += __shfl_xor_sync(0xffffffffu, o3, 1, 4);                         \
    o4 += __shfl_xor_sync(0xffffffffu, o4, 1, 4);                         \
    o5 += __shfl_xor_sync(0xffffffffu, o5, 1, 4);                         \
    o6 += __shfl_xor_sync(0xffffffffu, o6, 1, 4);                         \
    o7 += __shfl_xor_sync(0xffffffffu, o7, 1, 4);                         \
    o0 += __shfl_xor_sync(0xffffffffu, o0, 2, 4);                         \
    o1 += __shfl_xor_sync(0xffffffffu, o1, 2, 4);                         \
    o2 += __shfl_xor_sync(0xffffffffu, o2, 2, 4);                         \
    o3 += __shfl_xor_sync(0xffffffffu, o3, 2, 4);                         \
    o4 += __shfl_xor_sync(0xffffffffu, o4, 2, 4);                         \
    o5 += __shfl_xor_sync(0xffffffffu, o5, 2, 4);                         \
    o6 += __shfl_xor_sync(0xffffffffu, o6, 2, 4);                         \
    o7 += __shfl_xor_sync(0xffffffffu, o7, 2, 4);                         \
    o0 += sbo[0]; o1 += sbo[1]; o2 += sbo[2]; o3 += sbo[3];               \
    o4 += sbo[4]; o5 += sbo[5]; o6 += sbo[6]; o7 += sbo[7];               \
    float wa, wb2;                                                        \
    if      (q == 0) { wa = o0; wb2 = o1; }                               \
    else if (q == 1) { wa = o2; wb2 = o3; }                               \
    else if (q == 2) { wa = o4; wb2 = o5; }                               \
    else             { wa = o6; wb2 = o7; }                               \
    if (VALID) {                                                          \
        int f = 2 * q;                                                    \
        float* op = out + (size_t)(NODE) * 32 + o;                        \
        op[f * 4]       = wa;                                             \
        op[(f + 1) * 4] = wb2;                                            \
        if (o < 3) {                                                      \
            float ns = g_nself[(NODE)];                                   \
            float* hbp = g_hbuf[o & 1] + (size_t)(NODE) * 8;              \
            float* psp = g_Px + (size_t)(NODE) * ROWF + (8 + o) * 8;      \
            hbp[f]     = wa;                                              \
            hbp[f + 1] = wb2;                                             \
            psp[f]     = ns * wa;                                         \
            psp[f + 1] = ns * wb2;                                        \
        }                                                                 \
    }                                                                     \
} while (0)

// Fused 8-step GRU scan for one output iteration o.
// 4 lanes per node, TWO nodes per lane (block covers 64 nodes).
// gate = sigma(P@M + H@L_bot + fb).
// Prologue:
//   o == 0: gather-propagate ALL 8 initial x slices (+self) into Px slots 0-7
//           for this block's nodes (race-free: reads only inputs + norms).
//   o >  0: gather-propagate h into slot 7+o, reading g_hbuf[(o-1)&1] written
//           by the previous scan; this scan's epilogue writes g_hbuf[o&1],
//           so no intra-launch read/write conflict.
__global__ void __launch_bounds__(128)
k_scan(const float* __restrict__ x, const float* __restrict__ att,
       const float* __restrict__ Lzw, const float* __restrict__ Lrw,
       const float* __restrict__ Lhw,
       const float* __restrict__ Wout, const float* __restrict__ bout,
       float* __restrict__ out, int N, int o)
{
    __shared__ __align__(16) float sMz[128], sMr[128], sMh[128];
    __shared__ __align__(16) float sLz[256], sLr[256], sLh[256];   // L bottom halves
    __shared__ __align__(16) float sfbz[16], sfbr[16], sfbh[16];
    __shared__ __align__(16) float sWo[128], sbo[8], sp[8];

    int tid = threadIdx.x;
    if (tid < 128) {
        sMz[tid] = g_M[tid]; sMr[tid] = g_M[128 + tid]; sMh[tid] = g_M[256 + tid];
        sWo[tid] = Wout[tid];
    }
    for (int i = tid; i < 256; i += 128) {
        sLz[i] = Lzw[256 + i]; sLr[i] = Lrw[256 + i]; sLh[i] = Lhw[256 + i];
    }
    if (tid < 16) {
        sfbz[tid] = g_fb[tid]; sfbr[tid] = g_fb[16 + tid]; sfbh[tid] = g_fb[32 + tid];
    }
    if (tid < 8) {
        sbo[tid] = bout[tid];
        float v = att[tid];
        float m = v;
        m = fmaxf(m, __shfl_xor_sync(0xffu, m, 1, 8));
        m = fmaxf(m, __shfl_xor_sync(0xffu, m, 2, 8));
        m = fmaxf(m, __shfl_xor_sync(0xffu, m, 4, 8));
        float e = __expf(v - m);
        float s = e;
        s += __shfl_xor_sync(0xffu, s, 1, 8);
        s += __shfl_xor_sync(0xffu, s, 2, 8);
        s += __shfl_xor_sync(0xffu, s, 4, 8);
        sp[tid] = __fdividef(e, s);
    }

    // ---- fused gather prologue for this block's 64 nodes ----
    {
        int ln = tid >> 1;                         // local node 0..63
        int ng = blockIdx.x * 64 + ln;
        int fh = (tid & 1) * 4;                    // feature half: 0 or 4
        if (ng < N) {
            float dn = g_dinv[ng];
            if (o == 0) {
                // initial propagation of all 8 time slices for features fh..fh+3
                float ns = g_nself[ng];
                const float4* xb = (const float4*)(x + (size_t)ng * 64 + fh * 8);
                float4 a0 = xb[0], b0 = xb[1], a1 = xb[2], b1 = xb[3];
                float4 a2 = xb[4], b2 = xb[5], a3 = xb[6], b3 = xb[7];
                a0.x *= ns; a0.y *= ns; a0.z *= ns; a0.w *= ns;
                b0.x *= ns; b0.y *= ns; b0.z *= ns; b0.w *= ns;
                a1.x *= ns; a1.y *= ns; a1.z *= ns; a1.w *= ns;
                b1.x *= ns; b1.y *= ns; b1.z *= ns; b1.w *= ns;
                a2.x *= ns; a2.y *= ns; a2.z *= ns; a2.w *= ns;
                b2.x *= ns; b2.y *= ns; b2.z *= ns; b2.w *= ns;
                a3.x *= ns; a3.y *= ns; a3.z *= ns; a3.w *= ns;
                b3.x *= ns; b3.y *= ns; b3.z *= ns; b3.w *= ns;
                int beg = g_off[ng], end = beg + g_cnt[ng];
#pragma unroll 1
                for (int j = beg; j < end; j++) {
                    int s = g_csr[j];
                    float ne = dn * g_dinv[s];
                    const float4* xs = (const float4*)(x + (size_t)s * 64 + fh * 8);
                    float4 u0 = xs[0], v0 = xs[1], u1 = xs[2], v1 = xs[3];
                    float4 u2 = xs[4], v2 = xs[5], u3 = xs[6], v3 = xs[7];
                    a0.x = fmaf(u0.x, ne, a0.x); a0.y = fmaf(u0.y, ne, a0.y);
                    a0.z = fmaf(u0.z, ne, a0.z); a0.w = fmaf(u0.w, ne, a0.w);
                    b0.x = fmaf(v0.x, ne, b0.x); b0.y = fmaf(v0.y, ne, b0.y);
                    b0.z = fmaf(v0.z, ne, b0.z); b0.w = fmaf(v0.w, ne, b0.w);
                    a1.x = fmaf(u1.x, ne, a1.x); a1.y = fmaf(u1.y, ne, a1.y);
                    a1.z = fmaf(u1.z, ne, a1.z); a1.w = fmaf(u1.w, ne, a1.w);
                    b1.x = fmaf(v1.x, ne, b1.x); b1.y = fmaf(v1.y, ne, b1.y);
                    b1.z = fmaf(v1.z, ne, b1.z); b1.w = fmaf(v1.w, ne, b1.w);
                    a2.x = fmaf(u2.x, ne, a2.x); a2.y = fmaf(u2.y, ne, a2.y);
                    a2.z = fmaf(u2.z, ne, a2.z); a2.w = fmaf(u2.w, ne, a2.w);
                    b2.x = fmaf(v2.x, ne, b2.x); b2.y = fmaf(v2.y, ne, b2.y);
                    b2.z = fmaf(v2.z, ne, b2.z); b2.w = fmaf(v2.w, ne, b2.w);
                    a3.x = fmaf(u3.x, ne, a3.x); a3.y = fmaf(u3.y, ne, a3.y);
                    a3.z = fmaf(u3.z, ne, a3.z); a3.w = fmaf(u3.w, ne, a3.w);
                    b3.x = fmaf(v3.x, ne, b3.x); b3.y = fmaf(v3.y, ne, b3.y);
                    b3.z = fmaf(v3.z, ne, b3.z); b3.w = fmaf(v3.w, ne, b3.w);
                }
                // transpose-store: Px[ng][t][fh..fh+3]
                float* pr = g_Px + (size_t)ng * ROWF + fh;
                *(float4*)(pr + 0 * 8) = make_float4(a0.x, a1.x, a2.x, a3.x);
                *(float4*)(pr + 1 * 8) = make_float4(a0.y, a1.y, a2.y, a3.y);
                *(float4*)(pr + 2 * 8) = make_float4(a0.z, a1.z, a2.z, a3.z);
                *(float4*)(pr + 3 * 8) = make_float4(a0.w, a1.w, a2.w, a3.w);
                *(float4*)(pr + 4 * 8) = make_float4(b0.x, b1.x, b2.x, b3.x);
                *(float4*)(pr + 5 * 8) = make_float4(b0.y, b1.y, b2.y, b3.y);
                *(float4*)(pr + 6 * 8) = make_float4(b0.z, b1.z, b2.z, b3.z);
                *(float4*)(pr + 7 * 8) = make_float4(b0.w, b1.w, b2.w, b3.w);
            } else {
                // h propagation into slot 7+o, reading the PREVIOUS h buffer
                const float* hsrc = g_hbuf[(o - 1) & 1];
                float* pp = g_Px + (size_t)ng * ROWF + (7 + o) * 8 + fh;
                float4 acc = *(float4*)pp;         // self term from prev epilogue
                int beg = g_off[ng], end = beg + g_cnt[ng];
#pragma unroll 4
                for (int j = beg; j < end; j++) {
                    int s = g_csr[j];
                    float ne = dn * g_dinv[s];
                    float4 hv = *(const float4*)(hsrc + (size_t)s * 8 + fh);
                    acc.x = fmaf(hv.x, ne, acc.x);
                    acc.y = fmaf(hv.y, ne, acc.y);
                    acc.z = fmaf(hv.z, ne, acc.z);
                    acc.w = fmaf(hv.w, ne, acc.w);
                }
                *(float4*)pp = acc;
            }
        }
    }
    __syncthreads();

    int g = tid >> 2;
    int nodeA = blockIdx.x * 64 + g;
    int nodeB = nodeA + 32;
    bool validA = (nodeA < N);
    bool validB = (nodeB < N);
    if (nodeA >= N) nodeA = N - 1;
    if (nodeB >= N) nodeB = N - 1;
    int q  = tid & 3;
    int q4 = q * 4;

    float HA0 = 0.f, HA1 = 0.f, HA2 = 0.f, HA3 = 0.f;
    float HB0 = 0.f, HB1 = 0.f, HB2 = 0.f, HB3 = 0.f;
    float AA0 = 0.f, AA1 = 0.f, AA2 = 0.f, AA3 = 0.f;
    float AB0 = 0.f, AB1 = 0.f, AB2 = 0.f, AB3 = 0.f;

    const float* prowA = g_Px + (size_t)nodeA * ROWF + o * 8;
    const float* prowB = g_Px + (size_t)nodeB * ROWF + o * 8;

#pragma unroll 1
    for (int t = 0; t < 8; t++) {
        float4 qaA = ((const float4*)(prowA + t * 8))[0];
        float4 qbA = ((const float4*)(prowA + t * 8))[1];
        float4 qaB = ((const float4*)(prowB + t * 8))[0];
        float4 qbB = ((const float4*)(prowB + t * 8))[1];

        float hbA0, hbA1, hbA2, hbA3, hbA4, hbA5, hbA6, hbA7,
              hbA8, hbA9, hbA10, hbA11, hbA12, hbA13, hbA14, hbA15;
        float hbB0, hbB1, hbB2, hbB3, hbB4, hbB5, hbB6, hbB7,
              hbB8, hbB9, hbB10, hbB11, hbB12, hbB13, hbB14, hbB15;
        BCAST16(hbA, HA0, HA1, HA2, HA3);
        BCAST16(hbB, HB0, HB1, HB2, HB3);

        float ZA0, ZA1, ZA2, ZA3, ZB0, ZB1, ZB2, ZB3;
        float RA0, RA1, RA2, RA3, RB0, RB1, RB2, RB3;
        float TA0, TA1, TA2, TA3, TB0, TB1, TB2, TB3;

        {   // ---- z gate ----
            float4 bv = *(const float4*)(sfbz + q4);
            float cA0 = bv.x, cA1 = bv.y, cA2 = bv.z, cA3 = bv.w;
            float cB0 = bv.x, cB1 = bv.y, cB2 = bv.z, cB3 = bv.w;
            DOT8P2(sMz);
            DOT16H(sLz, hbA, hbB);
            ZA0 = sigmoid_f(cA0); ZA1 = sigmoid_f(cA1); ZA2 = sigmoid_f(cA2); ZA3 = sigmoid_f(cA3);
            ZB0 = sigmoid_f(cB0); ZB1 = sigmoid_f(cB1); ZB2 = sigmoid_f(cB2); ZB3 = sigmoid_f(cB3);
        }
        {   // ---- r gate -> H*R ----
            float4 bv = *(const float4*)(sfbr + q4);
            float cA0 = bv.x, cA1 = bv.y, cA2 = bv.z, cA3 = bv.w;
            float cB0 = bv.x, cB1 = bv.y, cB2 = bv.z, cB3 = bv.w;
            DOT8P2(sMr);
            DOT16H(sLr, hbA, hbB);
            RA0 = HA0 * sigmoid_f(cA0); RA1 = HA1 * sigmoid_f(cA1);
            RA2 = HA2 * sigmoid_f(cA2); RA3 = HA3 * sigmoid_f(cA3);
            RB0 = HB0 * sigmoid_f(cB0); RB1 = HB1 * sigmoid_f(cB1);
            RB2 = HB2 * sigmoid_f(cB2); RB3 = HB3 * sigmoid_f(cB3);
        }
        {   // ---- h gate ----
            BCAST16(hbA, RA0, RA1, RA2, RA3);   // reuse hb regs for H*R broadcast
            BCAST16(hbB, RB0, RB1, RB2, RB3);
            float4 bv = *(const float4*)(sfbh + q4);
            float cA0 = bv.x, cA1 = bv.y, cA2 = bv.z, cA3 = bv.w;
            float cB0 = bv.x, cB1 = bv.y, cB2 = bv.z, cB3 = bv.w;
            DOT8P2(sMh);
            DOT16H(sLh, hbA, hbB);
            TA0 = tanh_f(cA0); TA1 = tanh_f(cA1); TA2 = tanh_f(cA2); TA3 = tanh_f(cA3);
            TB0 = tanh_f(cB0); TB1 = tanh_f(cB1); TB2 = tanh_f(cB2); TB3 = tanh_f(cB3);
        }

        float pt = sp[t];
        HA0 = ZA0 * HA0 + (1.0f - ZA0) * TA0;  AA0 = fmaf(pt, HA0, AA0);
        HA1 = ZA1 * HA1 + (1.0f - ZA1) * TA1;  AA1 = fmaf(pt, HA1, AA1);
        HA2 = ZA2 * HA2 + (1.0f - ZA2) * TA2;  AA2 = fmaf(pt, HA2, AA2);
        HA3 = ZA3 * HA3 + (1.0f - ZA3) * TA3;  AA3 = fmaf(pt, HA3, AA3);
        HB0 = ZB0 * HB0 + (1.0f - ZB0) * TB0;  AB0 = fmaf(pt, HB0, AB0);
        HB1 = ZB1 * HB1 + (1.0f - ZB1) * TB1;  AB1 = fmaf(pt, HB1, AB1);
        HB2 = ZB2 * HB2 + (1.0f - ZB2) * TB2;  AB2 = fmaf(pt, HB2, AB2);
        HB3 = ZB3 * HB3 + (1.0f - ZB3) * TB3;  AB3 = fmaf(pt, HB3, AB3);
    }

#define OUTF(F) (fmaf(r0, sWo[(q4 + 0) * 8 + (F)],                        \
                 fmaf(r1, sWo[(q4 + 1) * 8 + (F)],                        \
                 fmaf(r2, sWo[(q4 + 2) * 8 + (F)],                        \
                      r3 * sWo[(q4 + 3) * 8 + (F)]))))
    EPILOGUE(AA0, AA1, AA2, AA3, nodeA, validA);
    EPILOGUE(AB0, AB1, AB2, AB3, nodeB, validB);
#undef OUTF
}

// ---------------------------------------------------------------------------
extern "C" void kernel_launch(void* const* d_in, const int* in_sizes, int n_in,
                              void* d_out, int out_size)
{
    const float* x    = (const float*)d_in[0];
    const int*   ei   = (const int*)d_in[1];
    const float* att  = (const float*)d_in[2];
    const float* Wz   = (const float*)d_in[3];
    const float* bz   = (const float*)d_in[4];
    const float* Lzw  = (const float*)d_in[5];
    const float* Lzb  = (const float*)d_in[6];
    const float* Wr   = (const float*)d_in[7];
    const float* br   = (const float*)d_in[8];
    const float* Lrw  = (const float*)d_in[9];
    const float* Lrb  = (const float*)d_in[10];
    const float* Wh   = (const float*)d_in[11];
    const float* bh   = (const float*)d_in[12];
    const float* Lhw  = (const float*)d_in[13];
    const float* Lhb  = (const float*)d_in[14];
    const float* Wout = (const float*)d_in[15];
    const float* bout = (const float*)d_in[16];
    float* out = (float*)d_out;

    int N = in_sizes[0] / (FND * TIN);
    int E = in_sizes[1] / 2;
    if (N > NN) N = NN;   // static scratch capacity guard
    if (E > EE) E = EE;

    const int TB = 256;
    // ---- CSR build + weight fold (once per launch) ----
    k_zero_int<<<(N + TB - 1) / TB, TB>>>(N);
    k_cnt<<<(E + TB - 1) / TB, TB>>>(ei, E);
    k_norm<<<(N + TB - 1) / TB, TB>>>(N);
    k_alloc<<<(N + 255) / 256, 256>>>(N);
    k_scatter<<<(E + TB - 1) / TB, TB>>>(ei, E);
    k_fold<<<1, 64>>>(Wz, bz, Lzw, Lzb, Wr, br, Lrw, Lrb, Wh, bh, Lhw, Lhb);

    for (int o = 0; o < TOUTN; o++) {
        k_scan<<<(N + 63) / 64, 128>>>(x, att, Lzw, Lrw, Lhw, Wout, bout, out, N, o);
    }
}